// round 7
// baseline (speedup 1.0000x reference)
#include <cuda_runtime.h>
#include <math.h>

// Problem constants (fixed by setup_inputs): N=1024 rows, D=128 features.
#define NROWS 1024
#define DDIM  128

// scale = 1 / (tau * sqrt(D)) with tau = 1, D = 128
#define SCALE 0.08838834764831843f
// BETA = 1.0 (instance alignment weight)

// ---------------------------------------------------------------------------
// Scratch (device globals — no allocation allowed)
// ---------------------------------------------------------------------------
__device__ float g_xn[NROWS];          // ||x_i||^2
__device__ float g_yn[2][NROWS];       // ||y_j||^2  (0: lpe, 1: aug)
__device__ float g_pos[2][NROWS];      // ||x_i - y_i|| * scale (diagonal term)
__device__ float g_denom[2][NROWS];    // sum_j exp(dist_ij)

__device__ __forceinline__ float warp_sum32(float v) {
#pragma unroll
    for (int o = 16; o; o >>= 1) v += __shfl_xor_sync(0xffffffffu, v, o);
    return v;
}

// ---------------------------------------------------------------------------
// Kernel 1: per-row norms, diagonal (positive) distances, zero denominators.
// One warp per row; lane l owns float4 at column l*4 (128 floats / 32 lanes).
// ---------------------------------------------------------------------------
__global__ void __launch_bounds__(256) init_kernel(const float* __restrict__ x,
                                                   const float* __restrict__ aug,
                                                   const float* __restrict__ lpe) {
    int gw   = (blockIdx.x * blockDim.x + threadIdx.x) >> 5;  // global warp = row
    int lane = threadIdx.x & 31;
    if (gw >= NROWS) return;

    const float4 v = *(const float4*)(x   + gw * DDIM + lane * 4);
    const float4 a = *(const float4*)(aug + gw * DDIM + lane * 4);
    const float4 p = *(const float4*)(lpe + gw * DDIM + lane * 4);

    float sx = v.x * v.x + v.y * v.y + v.z * v.z + v.w * v.w;
    float sa = a.x * a.x + a.y * a.y + a.z * a.z + a.w * a.w;
    float sp = p.x * p.x + p.y * p.y + p.z * p.z + p.w * p.w;

    float dx, d0 = 0.f, d1 = 0.f;
    dx = v.x - p.x; d0 += dx * dx;  dx = v.y - p.y; d0 += dx * dx;
    dx = v.z - p.z; d0 += dx * dx;  dx = v.w - p.w; d0 += dx * dx;
    dx = v.x - a.x; d1 += dx * dx;  dx = v.y - a.y; d1 += dx * dx;
    dx = v.z - a.z; d1 += dx * dx;  dx = v.w - a.w; d1 += dx * dx;

    sx = warp_sum32(sx);
    sa = warp_sum32(sa);
    sp = warp_sum32(sp);
    d0 = warp_sum32(d0);
    d1 = warp_sum32(d1);

    if (lane == 0) {
        g_xn[gw]       = sx;
        g_yn[0][gw]    = sp;   // center loss vs label_prompt_embedding
        g_yn[1][gw]    = sa;   // instance loss vs aug_x
        g_pos[0][gw]   = sqrtf(d0) * SCALE;
        g_pos[1][gw]   = sqrtf(d1) * SCALE;
        g_denom[0][gw] = 0.f;
        g_denom[1][gw] = 0.f;
    }
}

// ---------------------------------------------------------------------------
// Kernel 2: pairwise distance matrix via dot-product GEMM, fused exp + rowsum.
// Tile: 128x128 per block, BK=16, 256 threads, 8x8 register micro-tile.
// grid = (8 col tiles, 8 row tiles, 2 losses)
// ---------------------------------------------------------------------------
#define BM 128
#define BN 128
#define BK 16

__global__ void __launch_bounds__(256) dm_kernel(const float* __restrict__ x,
                                                 const float* __restrict__ y0,
                                                 const float* __restrict__ y1) {
    const int loss = blockIdx.z;
    const float* __restrict__ y = loss ? y1 : y0;

    const int rowBase = blockIdx.y * BM;
    const int colBase = blockIdx.x * BN;

    __shared__ float xs[BK][BM];   // transposed: xs[k][row]
    __shared__ float ys[BK][BN];   // transposed: ys[k][col]

    const int tid = threadIdx.x;
    const int tx  = tid & 15;      // 16 column groups
    const int ty  = tid >> 4;      // 16 row groups

    float acc[8][8];
#pragma unroll
    for (int i = 0; i < 8; i++)
#pragma unroll
        for (int j = 0; j < 8; j++) acc[i][j] = 0.f;

    for (int kk = 0; kk < DDIM; kk += BK) {
        // Load both tiles (128 rows x 16 k) transposed into smem.
        // 512 float4 per tile, 2 per thread.
#pragma unroll
        for (int l = 0; l < 2; l++) {
            int idx = l * 256 + tid;        // 0..511
            int r   = idx >> 2;             // 0..127
            int c4  = (idx & 3) * 4;        // 0,4,8,12
            float4 v = *(const float4*)(x + (rowBase + r) * DDIM + kk + c4);
            xs[c4 + 0][r] = v.x; xs[c4 + 1][r] = v.y;
            xs[c4 + 2][r] = v.z; xs[c4 + 3][r] = v.w;
            float4 w = *(const float4*)(y + (colBase + r) * DDIM + kk + c4);
            ys[c4 + 0][r] = w.x; ys[c4 + 1][r] = w.y;
            ys[c4 + 2][r] = w.z; ys[c4 + 3][r] = w.w;
        }
        __syncthreads();

#pragma unroll
        for (int k = 0; k < BK; k++) {
            float a[8], b[8];
            *(float4*)&a[0] = *(const float4*)&xs[k][ty * 4];
            *(float4*)&a[4] = *(const float4*)&xs[k][64 + ty * 4];
            *(float4*)&b[0] = *(const float4*)&ys[k][tx * 4];
            *(float4*)&b[4] = *(const float4*)&ys[k][64 + tx * 4];
#pragma unroll
            for (int i = 0; i < 8; i++)
#pragma unroll
                for (int j = 0; j < 8; j++)
                    acc[i][j] = fmaf(a[i], b[j], acc[i][j]);
        }
        __syncthreads();
    }

    // Epilogue: dist = sqrt(||x||^2 + ||y||^2 - 2 dot) * scale; exp; row-sum.
    const int rbase = rowBase + ty * 4;
    const int cbase = colBase + tx * 4;

    float nx[8], ny[8];
#pragma unroll
    for (int i = 0; i < 4; i++) {
        nx[i]     = g_xn[rbase + i];
        nx[i + 4] = g_xn[rbase + 64 + i];
        ny[i]     = g_yn[loss][cbase + i];
        ny[i + 4] = g_yn[loss][cbase + 64 + i];
    }

    float rs[8];
#pragma unroll
    for (int i = 0; i < 8; i++) rs[i] = 0.f;

#pragma unroll
    for (int i = 0; i < 8; i++) {
#pragma unroll
        for (int j = 0; j < 8; j++) {
            float d2 = fmaxf(nx[i] + ny[j] - 2.f * acc[i][j], 0.f);
            rs[i] += __expf(sqrtf(d2) * SCALE);
        }
    }

    // Reduce across tx (16 lanes of a half-warp; lane = (ty&1)*16 + tx).
#pragma unroll
    for (int o = 8; o; o >>= 1) {
#pragma unroll
        for (int i = 0; i < 8; i++)
            rs[i] += __shfl_xor_sync(0xffffffffu, rs[i], o);
    }

    if (tx == 0) {
#pragma unroll
        for (int i = 0; i < 4; i++) {
            atomicAdd(&g_denom[loss][rbase + i],      rs[i]);
            atomicAdd(&g_denom[loss][rbase + 64 + i], rs[i + 4]);
        }
    }
}

// ---------------------------------------------------------------------------
// Kernel 3: per-row loss value, block reduction, mean, final 3 scalars.
// ---------------------------------------------------------------------------
__global__ void __launch_bounds__(1024) final_kernel(float* __restrict__ out) {
    const int i    = threadIdx.x;
    const int warp = i >> 5;
    const int lane = i & 31;

    float v0 = g_pos[0][i] - logf(g_denom[0][i]);
    float v1 = g_pos[1][i] - logf(g_denom[1][i]);

    __shared__ float s0[32], s1[32];
    v0 = warp_sum32(v0);
    v1 = warp_sum32(v1);
    if (lane == 0) { s0[warp] = v0; s1[warp] = v1; }
    __syncthreads();

    if (warp == 0) {
        float a0 = s0[lane];
        float a1 = s1[lane];
        a0 = warp_sum32(a0);
        a1 = warp_sum32(a1);
        if (lane == 0) {
            float center   = a0 * (1.0f / NROWS);
            float instance = a1 * (1.0f / NROWS);
            out[0] = center + instance;   // alignment_loss (beta = 1)
            out[1] = center;              // center_alignment_loss
            out[2] = instance;            // instance_alignment_loss
        }
    }
}

// ---------------------------------------------------------------------------
// Entry point
// ---------------------------------------------------------------------------
extern "C" void kernel_launch(void* const* d_in, const int* in_sizes, int n_in,
                              void* d_out, int out_size) {
    const float* x   = (const float*)d_in[0];  // x [1024,128]
    const float* aug = (const float*)d_in[1];  // aug_x
    const float* lpe = (const float*)d_in[2];  // label_prompt_embedding
    float* out = (float*)d_out;

    // 1024 warps (one per row): 128 blocks x 256 threads
    init_kernel<<<128, 256>>>(x, aug, lpe);

    dim3 grid(NROWS / BN, NROWS / BM, 2);      // (8, 8, 2)
    dm_kernel<<<grid, 256>>>(x, lpe, aug);

    final_kernel<<<1, 1024>>>(out);
}